// round 14
// baseline (speedup 1.0000x reference)
#include <cuda_runtime.h>
#include <cuda_bf16.h>
#include <cstdint>

#define BB 2
#define CC 72
#define NN 9216
#define TQ 128
#define TK 128
#define NT 72
#define NQT 72

// bf16 hi/lo pre-split operands.
// Q,K token-major [b][n][72]; V channel-major [b][c][n].
__device__ __align__(16) __nv_bfloat16 g_qh[(size_t)BB * NN * CC];
__device__ __align__(16) __nv_bfloat16 g_ql[(size_t)BB * NN * CC];
__device__ __align__(16) __nv_bfloat16 g_kh[(size_t)BB * NN * CC];
__device__ __align__(16) __nv_bfloat16 g_kl[(size_t)BB * NN * CC];
__device__ __align__(16) __nv_bfloat16 g_vh[(size_t)BB * CC * NN];
__device__ __align__(16) __nv_bfloat16 g_vl[(size_t)BB * CC * NN];

// ---- flash smem layout (bytes). Q/K rows 176B, V rows 272B.
#define HL     22528u
#define K_OFF  45056u
#define KBUF   45056u
#define V_OFF  135168u
#define VBUF   39168u
#define VHL    19584u
#define KSTR   176u
#define VSTR   272u
#define SM_TOTAL 213504
// epilogue overlays the K region
#define OS0_OFF 45056u              // [128][73] f32
#define OS1_OFF (45056u + 37376u)
#define LR_OFF  (45056u + 74752u)   // 2 x [128] f32

// ---------------------------------------------------------------------------
__device__ __forceinline__ uint32_t smem_u32(const void* p) {
    uint32_t a;
    asm("{ .reg .u64 t; cvta.to.shared.u64 t, %1; cvt.u32.u64 %0, t; }" : "=r"(a) : "l"(p));
    return a;
}
__device__ __forceinline__ uint32_t lds32(uint32_t a) {
    uint32_t v;
    asm volatile("ld.shared.b32 %0, [%1];" : "=r"(v) : "r"(a));
    return v;
}
__device__ __forceinline__ void sts128z(uint32_t a) {
    asm volatile("st.shared.v4.b32 [%0], {%1,%1,%1,%1};" :: "r"(a), "r"(0u) : "memory");
}
__device__ __forceinline__ void cpa16(uint32_t dst, const void* src) {
    asm volatile("cp.async.cg.shared.global [%0], [%1], 16;" :: "r"(dst), "l"(src));
}
__device__ __forceinline__ void cpa_commit() { asm volatile("cp.async.commit_group;" ::: "memory"); }
__device__ __forceinline__ void cpa_wait0()  { asm volatile("cp.async.wait_group 0;" ::: "memory"); }

__device__ __forceinline__ void mma16816(float* d,
                                         uint32_t a0, uint32_t a1, uint32_t a2, uint32_t a3,
                                         uint32_t b0, uint32_t b1) {
    asm volatile(
        "mma.sync.aligned.m16n8k16.row.col.f32.bf16.bf16.f32 "
        "{%0,%1,%2,%3}, {%4,%5,%6,%7}, {%8,%9}, {%0,%1,%2,%3};"
        : "+f"(d[0]), "+f"(d[1]), "+f"(d[2]), "+f"(d[3])
        : "r"(a0), "r"(a1), "r"(a2), "r"(a3), "r"(b0), "r"(b1));
}
__device__ __forceinline__ uint32_t packbf(float lo, float hi) {
    uint32_t r;
    asm("cvt.rn.bf16x2.f32 %0, %1, %2;" : "=r"(r) : "f"(hi), "f"(lo));
    return r;
}
__device__ __forceinline__ float lo16f(uint32_t p) { return __uint_as_float(p << 16); }
__device__ __forceinline__ float hi16f(uint32_t p) { return __uint_as_float(p & 0xFFFF0000u); }
__device__ __forceinline__ float ex2f(float x) {
    float y;
    asm("ex2.approx.f32 %0, %1;" : "=f"(y) : "f"(x));
    return y;
}

// ---------------------------------------------------------------------------
// Kernel A: QKV projection + hi/lo split. Q (and bq) pre-scaled by log2(e)
// so flash can use ex2 directly. grid = 144, 256 threads.
// ---------------------------------------------------------------------------
extern "C" __global__ void __launch_bounds__(256, 1)
qkv_kernel(const float* __restrict__ x,
           const float* __restrict__ Wq, const float* __restrict__ bq,
           const float* __restrict__ Wk, const float* __restrict__ bk,
           const float* __restrict__ Wv, const float* __restrict__ bv)
{
    extern __shared__ float sm[];
    float* Xs = sm;                                   // [72][128]
    float* Ws = Xs + CC * TQ;                         // 3 x [72(c)][72(d)]
    __nv_bfloat16* St = (__nv_bfloat16*)(Ws + 3 * CC * CC);  // [2][128*72]

    const int b  = blockIdx.x / NQT;
    const int n0 = (blockIdx.x % NQT) * TQ;
    const int t  = threadIdx.x;

    for (int idx = t; idx < CC * TQ; idx += 256) {
        int c = idx / TQ, n = idx % TQ;
        Xs[idx] = x[(size_t)b * CC * NN + (size_t)c * NN + n0 + n];
    }
    #pragma unroll
    for (int m = 0; m < 3; m++) {
        const float* Wg = (m == 0) ? Wq : (m == 1) ? Wk : Wv;
        for (int idx = t; idx < CC * CC; idx += 256) {
            int d = idx / CC, c = idx % CC;
            Ws[m * CC * CC + c * CC + d] = Wg[idx];
        }
    }
    __syncthreads();

    const int dg = t >> 5;   // 8 groups x 9 d
    const int nc = t & 31;   // 32 groups x 4 n

    #pragma unroll
    for (int m = 0; m < 3; m++) {
        const float* bias = (m == 0) ? bq : (m == 1) ? bk : bv;
        const float* W = Ws + m * CC * CC;
        float acc[9][4];
        #pragma unroll
        for (int dd = 0; dd < 9; dd++) {
            float bbv = bias[dg * 9 + dd];
            #pragma unroll
            for (int k = 0; k < 4; k++) acc[dd][k] = bbv;
        }
        for (int c = 0; c < CC; c++) {
            float4 xv = *(const float4*)&Xs[c * TQ + nc * 4];
            const float* wc = &W[c * CC + dg * 9];
            #pragma unroll
            for (int dd = 0; dd < 9; dd++) {
                float w = wc[dd];
                acc[dd][0] += w * xv.x; acc[dd][1] += w * xv.y;
                acc[dd][2] += w * xv.z; acc[dd][3] += w * xv.w;
            }
        }
        if (m == 0) {   // fold log2(e) into Q so exp(s) == ex2(s')
            #pragma unroll
            for (int dd = 0; dd < 9; dd++)
                #pragma unroll
                for (int k = 0; k < 4; k++) acc[dd][k] *= 1.4426950408889634f;
        }
        if (m < 2) {
            #pragma unroll
            for (int k = 0; k < 4; k++) {
                int row = nc * 4 + k;
                #pragma unroll
                for (int dd = 0; dd < 9; dd++) {
                    float v = acc[dd][k];
                    __nv_bfloat16 h = __float2bfloat16(v);
                    St[row * CC + dg * 9 + dd] = h;
                    St[9216 + row * CC + dg * 9 + dd] = __float2bfloat16(v - __bfloat162float(h));
                }
            }
            __syncthreads();
            const uint4* src = (const uint4*)St;
            uint4* dh = (uint4*)((m == 0 ? g_qh : g_kh) + ((size_t)b * NN + n0) * CC);
            uint4* dl = (uint4*)((m == 0 ? g_ql : g_kl) + ((size_t)b * NN + n0) * CC);
            #pragma unroll
            for (int r = 0; r < 5; r++) {
                int idx = t + r * 256;
                if (idx < 1152) { dh[idx] = src[idx]; dl[idx] = src[1152 + idx]; }
            }
            __syncthreads();
        } else {
            #pragma unroll
            for (int dd = 0; dd < 9; dd++) {
                size_t cbase = ((size_t)b * CC + dg * 9 + dd) * NN + n0 + nc * 4;
                uint32_t w01 = packbf(acc[dd][0], acc[dd][1]);
                uint32_t w23 = packbf(acc[dd][2], acc[dd][3]);
                uint32_t l01 = packbf(acc[dd][0] - lo16f(w01), acc[dd][1] - hi16f(w01));
                uint32_t l23 = packbf(acc[dd][2] - lo16f(w23), acc[dd][3] - hi16f(w23));
                *(uint2*)&g_vh[cbase] = make_uint2(w01, w23);
                *(uint2*)&g_vl[cbase] = make_uint2(l01, l23);
            }
        }
    }
}

// ---------------------------------------------------------------------------
// tile loaders (256 threads)
// ---------------------------------------------------------------------------
__device__ __forceinline__ void load_q(uint32_t sb, int tid, int b, int i0) {
    #pragma unroll
    for (int it = 0; it < 9; it++) {
        int idx = tid + it * 256;          // 0..2303
        int m = idx / 1152;
        int rem = idx - m * 1152;
        int r = rem / 9, ch = rem - r * 9;
        const __nv_bfloat16* src = (m ? g_ql : g_qh) + ((size_t)b * NN + i0 + r) * CC + ch * 8;
        cpa16(sb + m * HL + r * KSTR + ch * 16, src);
    }
}
__device__ __forceinline__ void load_kv(uint32_t sb, int tid, int b, int j0, int buf) {
    const uint32_t kbase = sb + K_OFF + buf * KBUF;
    const uint32_t vbase = sb + V_OFF + buf * VBUF;
    #pragma unroll
    for (int it = 0; it < 9; it++) {
        int idx = tid + it * 256;
        int m = idx / 1152;
        int rem = idx - m * 1152;
        int r = rem / 9, ch = rem - r * 9;
        const __nv_bfloat16* src = (m ? g_kl : g_kh) + ((size_t)b * NN + j0 + r) * CC + ch * 8;
        cpa16(kbase + m * HL + r * KSTR + ch * 16, src);
    }
    #pragma unroll
    for (int it = 0; it < 9; it++) {
        int idx = tid + it * 256;
        int m = idx / 1152;
        int rem = idx - m * 1152;
        int r = rem >> 4, ch = rem & 15;
        const __nv_bfloat16* src = (m ? g_vl : g_vh) + ((size_t)b * CC + r) * NN + j0 + ch * 8;
        cpa16(vbase + m * VHL + r * VSTR + ch * 16, src);
    }
}

// ---------------------------------------------------------------------------
// Kernel B: HMMA flash attention (bf16x3), 256 threads / 8 warps.
// Each warp: m=32 query rows (2 row-blocks) x n=64 K-columns.
// exp/pack fused into GEMM2 per 16-column chunk (keeps regs low, overlaps
// MUFU with tensor work).
// ---------------------------------------------------------------------------
extern "C" __global__ void __launch_bounds__(256, 1)
flash_kernel(const float* __restrict__ x, float* __restrict__ out)
{
    extern __shared__ char smc[];
    const uint32_t sb = smem_u32(smc);

    const int b   = blockIdx.x / NQT;
    const int i0  = (blockIdx.x % NQT) * TQ;
    const int tid = threadIdx.x;
    const int w   = tid >> 5;
    const int lane = tid & 31;
    const int g   = lane >> 2;
    const int q   = lane & 3;
    const int wq  = w >> 1;       // query 32-row group (0..3)
    const int wh  = w & 1;        // column/k half (0..1)

    // ---- zero the c-padding of Q(hi,lo) + both K buffers (6 matrices x 128 rows)
    #pragma unroll
    for (int it = 0; it < 3; it++) {
        int idx = tid + it * 256;
        uint32_t a = sb + (idx >> 7) * 22528u + (idx & 127) * KSTR + 144u;
        sts128z(a); sts128z(a + 16u);
    }
    load_q(sb, tid, b, i0);
    load_kv(sb, tid, b, 0, 0);
    cpa_commit();
    cpa_wait0();
    __syncthreads();

    float oacc[2][9][4];
    #pragma unroll
    for (int rb = 0; rb < 2; rb++)
        #pragma unroll
        for (int nb = 0; nb < 9; nb++)
            #pragma unroll
            for (int k = 0; k < 4; k++) oacc[rb][nb][k] = 0.f;
    float lsum[2][2] = {{0.f, 0.f}, {0.f, 0.f}};

    // A-frag row bases: rows 32*wq + 16*rb + g (and +8)
    const uint32_t qa0 = sb + (32 * wq + g) * KSTR + q * 4;
    const uint32_t qa1 = qa0 + 16 * KSTR;

    for (int t = 0; t < NT; t++) {
        const int cb = t & 1;
        if (t + 1 < NT) load_kv(sb, tid, b, (t + 1) * TK, (t + 1) & 1);
        cpa_commit();

        // ========== GEMM1: S[32 x 64] = Q K^T, 3-pass bf16 ==========
        float sacc[2][8][4];
        #pragma unroll
        for (int rb = 0; rb < 2; rb++)
            #pragma unroll
            for (int nb = 0; nb < 8; nb++)
                #pragma unroll
                for (int k = 0; k < 4; k++) sacc[rb][nb][k] = 0.f;

        const uint32_t kb = sb + K_OFF + cb * KBUF + (g + 64 * wh) * KSTR + q * 4;
        #pragma unroll
        for (int ks = 0; ks < 5; ks++) {
            uint32_t Ah[2][4], Al[2][4];
            #pragma unroll
            for (int rb = 0; rb < 2; rb++) {
                const uint32_t ao = (rb ? qa1 : qa0) + ks * 32;
                Ah[rb][0] = lds32(ao);               Ah[rb][2] = lds32(ao + 16);
                Ah[rb][1] = lds32(ao + 8 * KSTR);    Ah[rb][3] = lds32(ao + 8 * KSTR + 16);
                Al[rb][0] = lds32(ao + HL);          Al[rb][2] = lds32(ao + HL + 16);
                Al[rb][1] = lds32(ao + HL + 8 * KSTR); Al[rb][3] = lds32(ao + HL + 8 * KSTR + 16);
            }
            #pragma unroll
            for (int nb = 0; nb < 8; nb++) {
                const uint32_t ba = kb + nb * (8 * KSTR) + ks * 32;
                uint32_t bh0 = lds32(ba), bh1 = lds32(ba + 16);
                uint32_t bl0 = lds32(ba + HL), bl1 = lds32(ba + HL + 16);
                #pragma unroll
                for (int rb = 0; rb < 2; rb++) {
                    mma16816(sacc[rb][nb], Ah[rb][0], Ah[rb][1], Ah[rb][2], Ah[rb][3], bh0, bh1);
                    mma16816(sacc[rb][nb], Ah[rb][0], Ah[rb][1], Ah[rb][2], Ah[rb][3], bl0, bl1);
                    mma16816(sacc[rb][nb], Al[rb][0], Al[rb][1], Al[rb][2], Al[rb][3], bh0, bh1);
                }
            }
        }

        // ===== fused: per 16-col chunk — exp+pack then GEMM2 (3-pass) =====
        const uint32_t vb = sb + V_OFF + cb * VBUF + g * VSTR + q * 4 + wh * 128;
        #pragma unroll
        for (int ks = 0; ks < 4; ks++) {
            uint32_t pA[2][2], pB[2][2], lA[2][2], lB[2][2];
            #pragma unroll
            for (int rb = 0; rb < 2; rb++) {
                float e0 = ex2f(sacc[rb][2 * ks][0]), e1 = ex2f(sacc[rb][2 * ks][1]);
                float e2 = ex2f(sacc[rb][2 * ks][2]), e3 = ex2f(sacc[rb][2 * ks][3]);
                float f0 = ex2f(sacc[rb][2 * ks + 1][0]), f1 = ex2f(sacc[rb][2 * ks + 1][1]);
                float f2 = ex2f(sacc[rb][2 * ks + 1][2]), f3 = ex2f(sacc[rb][2 * ks + 1][3]);
                lsum[rb][0] += e0 + e1 + f0 + f1;
                lsum[rb][1] += e2 + e3 + f2 + f3;
                uint32_t h01 = packbf(e0, e1), h23 = packbf(e2, e3);
                uint32_t g01 = packbf(f0, f1), g23 = packbf(f2, f3);
                pA[rb][0] = h01; pA[rb][1] = h23;
                pB[rb][0] = g01; pB[rb][1] = g23;
                lA[rb][0] = packbf(e0 - lo16f(h01), e1 - hi16f(h01));
                lA[rb][1] = packbf(e2 - lo16f(h23), e3 - hi16f(h23));
                lB[rb][0] = packbf(f0 - lo16f(g01), f1 - hi16f(g01));
                lB[rb][1] = packbf(f2 - lo16f(g23), f3 - hi16f(g23));
            }
            #pragma unroll
            for (int nb = 0; nb < 9; nb++) {
                const uint32_t va = vb + nb * (8 * VSTR) + ks * 32;
                uint32_t bh0 = lds32(va), bh1 = lds32(va + 16);
                uint32_t bl0 = lds32(va + VHL), bl1 = lds32(va + VHL + 16);
                #pragma unroll
                for (int rb = 0; rb < 2; rb++) {
                    mma16816(oacc[rb][nb], pA[rb][0], pA[rb][1], pB[rb][0], pB[rb][1], bh0, bh1);
                    mma16816(oacc[rb][nb], pA[rb][0], pA[rb][1], pB[rb][0], pB[rb][1], bl0, bl1);
                    mma16816(oacc[rb][nb], lA[rb][0], lA[rb][1], lB[rb][0], lB[rb][1], bh0, bh1);
                }
            }
        }

        cpa_wait0();
        __syncthreads();
    }

    // ================= epilogue =================
    #pragma unroll
    for (int rb = 0; rb < 2; rb++)
        #pragma unroll
        for (int h = 0; h < 2; h++) {
            lsum[rb][h] += __shfl_xor_sync(0xFFFFFFFFu, lsum[rb][h], 1);
            lsum[rb][h] += __shfl_xor_sync(0xFFFFFFFFu, lsum[rb][h], 2);
        }

    __syncthreads();   // everyone done with K region before overlay

    float* Os = (float*)(smc + (wh ? OS1_OFF : OS0_OFF));
    float* lr = (float*)(smc + LR_OFF) + wh * 128;
    #pragma unroll
    for (int rb = 0; rb < 2; rb++) {
        const int r0 = 32 * wq + 16 * rb + g;
        #pragma unroll
        for (int nb = 0; nb < 9; nb++) {
            int c = 8 * nb + 2 * q;
            Os[r0 * 73 + c]           = oacc[rb][nb][0];
            Os[r0 * 73 + c + 1]       = oacc[rb][nb][1];
            Os[(r0 + 8) * 73 + c]     = oacc[rb][nb][2];
            Os[(r0 + 8) * 73 + c + 1] = oacc[rb][nb][3];
        }
        if (q == 0) { lr[r0] = lsum[rb][0]; lr[r0 + 8] = lsum[rb][1]; }
    }
    __syncthreads();

    // fused grouped pooling
    const float* O0  = (const float*)(smc + OS0_OFF);
    const float* O1  = (const float*)(smc + OS1_OFF);
    const float* lr0 = (const float*)(smc + LR_OFF);
    const int ii = tid & 127;
    const int hh = tid >> 7;                   // 0..1
    const float inv = 1.f / (lr0[ii] + lr0[128 + ii]);
    const float* xb = x + (size_t)b * CC * NN + i0 + ii;
    #pragma unroll
    for (int g2 = hh * 9; g2 < hh * 9 + 9; g2++) {
        float acc = 0.f;
        #pragma unroll
        for (int f = 0; f < 4; f++) {
            int c = 4 * g2 + f;
            acc += xb[(size_t)c * NN] * (O0[ii * 73 + c] + O1[ii * 73 + c]);
        }
        out[((size_t)b * (CC / 4) + g2) * NN + i0 + ii] = acc * inv;
    }
}

// ---------------------------------------------------------------------------
extern "C" void kernel_launch(void* const* d_in, const int* in_sizes, int n_in,
                              void* d_out, int out_size)
{
    const float* x  = (const float*)d_in[0];
    const float* Wq = (const float*)d_in[1];
    const float* bq = (const float*)d_in[2];
    const float* Wk = (const float*)d_in[3];
    const float* bk = (const float*)d_in[4];
    const float* Wv = (const float*)d_in[5];
    const float* bv = (const float*)d_in[6];
    float* out = (float*)d_out;

    const size_t shq = (size_t)(CC * TQ + 3 * CC * CC) * sizeof(float)
                     + 2u * 9216u * sizeof(__nv_bfloat16);
    cudaFuncSetAttribute(qkv_kernel,   cudaFuncAttributeMaxDynamicSharedMemorySize, (int)shq);
    cudaFuncSetAttribute(flash_kernel, cudaFuncAttributeMaxDynamicSharedMemorySize, SM_TOTAL);

    qkv_kernel<<<BB * NQT, 256, shq>>>(x, Wq, bq, Wk, bk, Wv, bv);
    flash_kernel<<<BB * NQT, 256, SM_TOTAL>>>(x, out);
}

// round 17
// speedup vs baseline: 1.0050x; 1.0050x over previous
#include <cuda_runtime.h>
#include <cuda_bf16.h>
#include <cstdint>

#define BB 2
#define CC 72
#define NN 9216
#define TQ 128
#define TK 128
#define NT 72
#define NQT 72

// bf16 hi/lo pre-split operands.
// Q,K token-major [b][n][72]; V channel-major [b][c][n].
__device__ __align__(16) __nv_bfloat16 g_qh[(size_t)BB * NN * CC];
__device__ __align__(16) __nv_bfloat16 g_ql[(size_t)BB * NN * CC];
__device__ __align__(16) __nv_bfloat16 g_kh[(size_t)BB * NN * CC];
__device__ __align__(16) __nv_bfloat16 g_kl[(size_t)BB * NN * CC];
__device__ __align__(16) __nv_bfloat16 g_vh[(size_t)BB * CC * NN];
__device__ __align__(16) __nv_bfloat16 g_vl[(size_t)BB * CC * NN];

// ---- flash smem layout (bytes). Q/K rows 176B, V rows 272B.
#define HL     22528u
#define K_OFF  45056u
#define KBUF   45056u
#define V_OFF  135168u
#define VBUF   39168u
#define VHL    19584u
#define KSTR   176u
#define VSTR   272u
#define SM_TOTAL 213504
// epilogue overlays the K region
#define OS0_OFF 45056u              // [128][73] f32
#define OS1_OFF (45056u + 37376u)
#define LR_OFF  (45056u + 74752u)   // 2 x [128] f32

// ---------------------------------------------------------------------------
__device__ __forceinline__ uint32_t smem_u32(const void* p) {
    uint32_t a;
    asm("{ .reg .u64 t; cvta.to.shared.u64 t, %1; cvt.u32.u64 %0, t; }" : "=r"(a) : "l"(p));
    return a;
}
__device__ __forceinline__ uint32_t lds32(uint32_t a) {
    uint32_t v;
    asm volatile("ld.shared.b32 %0, [%1];" : "=r"(v) : "r"(a));
    return v;
}
__device__ __forceinline__ void sts128z(uint32_t a) {
    asm volatile("st.shared.v4.b32 [%0], {%1,%1,%1,%1};" :: "r"(a), "r"(0u) : "memory");
}
__device__ __forceinline__ void cpa16(uint32_t dst, const void* src) {
    asm volatile("cp.async.cg.shared.global [%0], [%1], 16;" :: "r"(dst), "l"(src));
}
__device__ __forceinline__ void cpa_commit() { asm volatile("cp.async.commit_group;" ::: "memory"); }
__device__ __forceinline__ void cpa_wait0()  { asm volatile("cp.async.wait_group 0;" ::: "memory"); }

__device__ __forceinline__ void mma16816(float* d,
                                         uint32_t a0, uint32_t a1, uint32_t a2, uint32_t a3,
                                         uint32_t b0, uint32_t b1) {
    asm volatile(
        "mma.sync.aligned.m16n8k16.row.col.f32.bf16.bf16.f32 "
        "{%0,%1,%2,%3}, {%4,%5,%6,%7}, {%8,%9}, {%0,%1,%2,%3};"
        : "+f"(d[0]), "+f"(d[1]), "+f"(d[2]), "+f"(d[3])
        : "r"(a0), "r"(a1), "r"(a2), "r"(a3), "r"(b0), "r"(b1));
}
__device__ __forceinline__ uint32_t packbf(float lo, float hi) {
    uint32_t r;
    asm("cvt.rn.bf16x2.f32 %0, %1, %2;" : "=r"(r) : "f"(hi), "f"(lo));
    return r;
}
__device__ __forceinline__ float lo16f(uint32_t p) { return __uint_as_float(p << 16); }
__device__ __forceinline__ float hi16f(uint32_t p) { return __uint_as_float(p & 0xFFFF0000u); }
__device__ __forceinline__ float ex2f(float x) {
    float y;
    asm("ex2.approx.f32 %0, %1;" : "=f"(y) : "f"(x));
    return y;
}

// ---------------------------------------------------------------------------
// Kernel A: QKV projection + hi/lo split. Q (and bq) pre-scaled by log2(e)
// so flash can use ex2 directly. grid = 144, 256 threads.
// ---------------------------------------------------------------------------
extern "C" __global__ void __launch_bounds__(256, 1)
qkv_kernel(const float* __restrict__ x,
           const float* __restrict__ Wq, const float* __restrict__ bq,
           const float* __restrict__ Wk, const float* __restrict__ bk,
           const float* __restrict__ Wv, const float* __restrict__ bv)
{
    extern __shared__ float sm[];
    float* Xs = sm;                                   // [72][128]
    float* Ws = Xs + CC * TQ;                         // 3 x [72(c)][72(d)]
    __nv_bfloat16* St = (__nv_bfloat16*)(Ws + 3 * CC * CC);  // [2][128*72]

    const int b  = blockIdx.x / NQT;
    const int n0 = (blockIdx.x % NQT) * TQ;
    const int t  = threadIdx.x;

    for (int idx = t; idx < CC * TQ; idx += 256) {
        int c = idx / TQ, n = idx % TQ;
        Xs[idx] = x[(size_t)b * CC * NN + (size_t)c * NN + n0 + n];
    }
    #pragma unroll
    for (int m = 0; m < 3; m++) {
        const float* Wg = (m == 0) ? Wq : (m == 1) ? Wk : Wv;
        for (int idx = t; idx < CC * CC; idx += 256) {
            int d = idx / CC, c = idx % CC;
            Ws[m * CC * CC + c * CC + d] = Wg[idx];
        }
    }
    __syncthreads();

    const int dg = t >> 5;   // 8 groups x 9 d
    const int nc = t & 31;   // 32 groups x 4 n

    #pragma unroll
    for (int m = 0; m < 3; m++) {
        const float* bias = (m == 0) ? bq : (m == 1) ? bk : bv;
        const float* W = Ws + m * CC * CC;
        float acc[9][4];
        #pragma unroll
        for (int dd = 0; dd < 9; dd++) {
            float bbv = bias[dg * 9 + dd];
            #pragma unroll
            for (int k = 0; k < 4; k++) acc[dd][k] = bbv;
        }
        for (int c = 0; c < CC; c++) {
            float4 xv = *(const float4*)&Xs[c * TQ + nc * 4];
            const float* wc = &W[c * CC + dg * 9];
            #pragma unroll
            for (int dd = 0; dd < 9; dd++) {
                float w = wc[dd];
                acc[dd][0] += w * xv.x; acc[dd][1] += w * xv.y;
                acc[dd][2] += w * xv.z; acc[dd][3] += w * xv.w;
            }
        }
        if (m == 0) {   // fold log2(e) into Q so exp(s) == ex2(s')
            #pragma unroll
            for (int dd = 0; dd < 9; dd++)
                #pragma unroll
                for (int k = 0; k < 4; k++) acc[dd][k] *= 1.4426950408889634f;
        }
        if (m < 2) {
            #pragma unroll
            for (int k = 0; k < 4; k++) {
                int row = nc * 4 + k;
                #pragma unroll
                for (int dd = 0; dd < 9; dd++) {
                    float v = acc[dd][k];
                    __nv_bfloat16 h = __float2bfloat16(v);
                    St[row * CC + dg * 9 + dd] = h;
                    St[9216 + row * CC + dg * 9 + dd] = __float2bfloat16(v - __bfloat162float(h));
                }
            }
            __syncthreads();
            const uint4* src = (const uint4*)St;
            uint4* dh = (uint4*)((m == 0 ? g_qh : g_kh) + ((size_t)b * NN + n0) * CC);
            uint4* dl = (uint4*)((m == 0 ? g_ql : g_kl) + ((size_t)b * NN + n0) * CC);
            #pragma unroll
            for (int r = 0; r < 5; r++) {
                int idx = t + r * 256;
                if (idx < 1152) { dh[idx] = src[idx]; dl[idx] = src[1152 + idx]; }
            }
            __syncthreads();
        } else {
            #pragma unroll
            for (int dd = 0; dd < 9; dd++) {
                size_t cbase = ((size_t)b * CC + dg * 9 + dd) * NN + n0 + nc * 4;
                uint32_t w01 = packbf(acc[dd][0], acc[dd][1]);
                uint32_t w23 = packbf(acc[dd][2], acc[dd][3]);
                uint32_t l01 = packbf(acc[dd][0] - lo16f(w01), acc[dd][1] - hi16f(w01));
                uint32_t l23 = packbf(acc[dd][2] - lo16f(w23), acc[dd][3] - hi16f(w23));
                *(uint2*)&g_vh[cbase] = make_uint2(w01, w23);
                *(uint2*)&g_vl[cbase] = make_uint2(l01, l23);
            }
        }
    }
}

// ---------------------------------------------------------------------------
// tile loaders (256 threads)
// ---------------------------------------------------------------------------
__device__ __forceinline__ void load_q(uint32_t sb, int tid, int b, int i0) {
    #pragma unroll
    for (int it = 0; it < 9; it++) {
        int idx = tid + it * 256;          // 0..2303
        int m = idx / 1152;
        int rem = idx - m * 1152;
        int r = rem / 9, ch = rem - r * 9;
        const __nv_bfloat16* src = (m ? g_ql : g_qh) + ((size_t)b * NN + i0 + r) * CC + ch * 8;
        cpa16(sb + m * HL + r * KSTR + ch * 16, src);
    }
}
__device__ __forceinline__ void load_kv(uint32_t sb, int tid, int b, int j0, int buf) {
    const uint32_t kbase = sb + K_OFF + buf * KBUF;
    const uint32_t vbase = sb + V_OFF + buf * VBUF;
    #pragma unroll
    for (int it = 0; it < 9; it++) {
        int idx = tid + it * 256;
        int m = idx / 1152;
        int rem = idx - m * 1152;
        int r = rem / 9, ch = rem - r * 9;
        const __nv_bfloat16* src = (m ? g_kl : g_kh) + ((size_t)b * NN + j0 + r) * CC + ch * 8;
        cpa16(kbase + m * HL + r * KSTR + ch * 16, src);
    }
    #pragma unroll
    for (int it = 0; it < 9; it++) {
        int idx = tid + it * 256;
        int m = idx / 1152;
        int rem = idx - m * 1152;
        int r = rem >> 4, ch = rem & 15;
        const __nv_bfloat16* src = (m ? g_vl : g_vh) + ((size_t)b * CC + r) * NN + j0 + ch * 8;
        cpa16(vbase + m * VHL + r * VSTR + ch * 16, src);
    }
}

// ---------------------------------------------------------------------------
// Kernel B: HMMA flash attention (bf16x3), 256 threads / 8 warps.
// Each warp: m=32 query rows (2 row-blocks) x n=64 K-columns.
// exp/pack fused into GEMM2 per 16-column chunk (keeps regs low, overlaps
// MUFU with tensor work).
// ---------------------------------------------------------------------------
extern "C" __global__ void __launch_bounds__(256, 1)
flash_kernel(const float* __restrict__ x, float* __restrict__ out)
{
    extern __shared__ char smc[];
    const uint32_t sb = smem_u32(smc);

    const int b   = blockIdx.x / NQT;
    const int i0  = (blockIdx.x % NQT) * TQ;
    const int tid = threadIdx.x;
    const int w   = tid >> 5;
    const int lane = tid & 31;
    const int g   = lane >> 2;
    const int q   = lane & 3;
    const int wq  = w >> 1;       // query 32-row group (0..3)
    const int wh  = w & 1;        // column/k half (0..1)

    // ---- zero the c-padding of Q(hi,lo) + both K buffers (6 matrices x 128 rows)
    #pragma unroll
    for (int it = 0; it < 3; it++) {
        int idx = tid + it * 256;
        uint32_t a = sb + (idx >> 7) * 22528u + (idx & 127) * KSTR + 144u;
        sts128z(a); sts128z(a + 16u);
    }
    load_q(sb, tid, b, i0);
    load_kv(sb, tid, b, 0, 0);
    cpa_commit();
    cpa_wait0();
    __syncthreads();

    float oacc[2][9][4];
    #pragma unroll
    for (int rb = 0; rb < 2; rb++)
        #pragma unroll
        for (int nb = 0; nb < 9; nb++)
            #pragma unroll
            for (int k = 0; k < 4; k++) oacc[rb][nb][k] = 0.f;
    float lsum[2][2] = {{0.f, 0.f}, {0.f, 0.f}};

    // A-frag row bases: rows 32*wq + 16*rb + g (and +8)
    const uint32_t qa0 = sb + (32 * wq + g) * KSTR + q * 4;
    const uint32_t qa1 = qa0 + 16 * KSTR;

    for (int t = 0; t < NT; t++) {
        const int cb = t & 1;
        if (t + 1 < NT) load_kv(sb, tid, b, (t + 1) * TK, (t + 1) & 1);
        cpa_commit();

        // ========== GEMM1: S[32 x 64] = Q K^T, 3-pass bf16 ==========
        float sacc[2][8][4];
        #pragma unroll
        for (int rb = 0; rb < 2; rb++)
            #pragma unroll
            for (int nb = 0; nb < 8; nb++)
                #pragma unroll
                for (int k = 0; k < 4; k++) sacc[rb][nb][k] = 0.f;

        const uint32_t kb = sb + K_OFF + cb * KBUF + (g + 64 * wh) * KSTR + q * 4;
        #pragma unroll
        for (int ks = 0; ks < 5; ks++) {
            uint32_t Ah[2][4], Al[2][4];
            #pragma unroll
            for (int rb = 0; rb < 2; rb++) {
                const uint32_t ao = (rb ? qa1 : qa0) + ks * 32;
                Ah[rb][0] = lds32(ao);               Ah[rb][2] = lds32(ao + 16);
                Ah[rb][1] = lds32(ao + 8 * KSTR);    Ah[rb][3] = lds32(ao + 8 * KSTR + 16);
                Al[rb][0] = lds32(ao + HL);          Al[rb][2] = lds32(ao + HL + 16);
                Al[rb][1] = lds32(ao + HL + 8 * KSTR); Al[rb][3] = lds32(ao + HL + 8 * KSTR + 16);
            }
            #pragma unroll
            for (int nb = 0; nb < 8; nb++) {
                const uint32_t ba = kb + nb * (8 * KSTR) + ks * 32;
                uint32_t bh0 = lds32(ba), bh1 = lds32(ba + 16);
                uint32_t bl0 = lds32(ba + HL), bl1 = lds32(ba + HL + 16);
                #pragma unroll
                for (int rb = 0; rb < 2; rb++) {
                    mma16816(sacc[rb][nb], Ah[rb][0], Ah[rb][1], Ah[rb][2], Ah[rb][3], bh0, bh1);
                    mma16816(sacc[rb][nb], Ah[rb][0], Ah[rb][1], Ah[rb][2], Ah[rb][3], bl0, bl1);
                    mma16816(sacc[rb][nb], Al[rb][0], Al[rb][1], Al[rb][2], Al[rb][3], bh0, bh1);
                }
            }
        }

        // ===== fused: per 16-col chunk — exp+pack then GEMM2 (3-pass) =====
        const uint32_t vb = sb + V_OFF + cb * VBUF + g * VSTR + q * 4 + wh * 128;
        #pragma unroll
        for (int ks = 0; ks < 4; ks++) {
            uint32_t pA[2][2], pB[2][2], lA[2][2], lB[2][2];
            #pragma unroll
            for (int rb = 0; rb < 2; rb++) {
                float e0 = ex2f(sacc[rb][2 * ks][0]), e1 = ex2f(sacc[rb][2 * ks][1]);
                float e2 = ex2f(sacc[rb][2 * ks][2]), e3 = ex2f(sacc[rb][2 * ks][3]);
                float f0 = ex2f(sacc[rb][2 * ks + 1][0]), f1 = ex2f(sacc[rb][2 * ks + 1][1]);
                float f2 = ex2f(sacc[rb][2 * ks + 1][2]), f3 = ex2f(sacc[rb][2 * ks + 1][3]);
                lsum[rb][0] += e0 + e1 + f0 + f1;
                lsum[rb][1] += e2 + e3 + f2 + f3;
                uint32_t h01 = packbf(e0, e1), h23 = packbf(e2, e3);
                uint32_t g01 = packbf(f0, f1), g23 = packbf(f2, f3);
                pA[rb][0] = h01; pA[rb][1] = h23;
                pB[rb][0] = g01; pB[rb][1] = g23;
                lA[rb][0] = packbf(e0 - lo16f(h01), e1 - hi16f(h01));
                lA[rb][1] = packbf(e2 - lo16f(h23), e3 - hi16f(h23));
                lB[rb][0] = packbf(f0 - lo16f(g01), f1 - hi16f(g01));
                lB[rb][1] = packbf(f2 - lo16f(g23), f3 - hi16f(g23));
            }
            #pragma unroll
            for (int nb = 0; nb < 9; nb++) {
                const uint32_t va = vb + nb * (8 * VSTR) + ks * 32;
                uint32_t bh0 = lds32(va), bh1 = lds32(va + 16);
                uint32_t bl0 = lds32(va + VHL), bl1 = lds32(va + VHL + 16);
                #pragma unroll
                for (int rb = 0; rb < 2; rb++) {
                    mma16816(oacc[rb][nb], pA[rb][0], pA[rb][1], pB[rb][0], pB[rb][1], bh0, bh1);
                    mma16816(oacc[rb][nb], pA[rb][0], pA[rb][1], pB[rb][0], pB[rb][1], bl0, bl1);
                    mma16816(oacc[rb][nb], lA[rb][0], lA[rb][1], lB[rb][0], lB[rb][1], bh0, bh1);
                }
            }
        }

        cpa_wait0();
        __syncthreads();
    }

    // ================= epilogue =================
    #pragma unroll
    for (int rb = 0; rb < 2; rb++)
        #pragma unroll
        for (int h = 0; h < 2; h++) {
            lsum[rb][h] += __shfl_xor_sync(0xFFFFFFFFu, lsum[rb][h], 1);
            lsum[rb][h] += __shfl_xor_sync(0xFFFFFFFFu, lsum[rb][h], 2);
        }

    __syncthreads();   // everyone done with K region before overlay

    float* Os = (float*)(smc + (wh ? OS1_OFF : OS0_OFF));
    float* lr = (float*)(smc + LR_OFF) + wh * 128;
    #pragma unroll
    for (int rb = 0; rb < 2; rb++) {
        const int r0 = 32 * wq + 16 * rb + g;
        #pragma unroll
        for (int nb = 0; nb < 9; nb++) {
            int c = 8 * nb + 2 * q;
            Os[r0 * 73 + c]           = oacc[rb][nb][0];
            Os[r0 * 73 + c + 1]       = oacc[rb][nb][1];
            Os[(r0 + 8) * 73 + c]     = oacc[rb][nb][2];
            Os[(r0 + 8) * 73 + c + 1] = oacc[rb][nb][3];
        }
        if (q == 0) { lr[r0] = lsum[rb][0]; lr[r0 + 8] = lsum[rb][1]; }
    }
    __syncthreads();

    // fused grouped pooling
    const float* O0  = (const float*)(smc + OS0_OFF);
    const float* O1  = (const float*)(smc + OS1_OFF);
    const float* lr0 = (const float*)(smc + LR_OFF);
    const int ii = tid & 127;
    const int hh = tid >> 7;                   // 0..1
    const float inv = 1.f / (lr0[ii] + lr0[128 + ii]);
    const float* xb = x + (size_t)b * CC * NN + i0 + ii;
    #pragma unroll
    for (int g2 = hh * 9; g2 < hh * 9 + 9; g2++) {
        float acc = 0.f;
        #pragma unroll
        for (int f = 0; f < 4; f++) {
            int c = 4 * g2 + f;
            acc += xb[(size_t)c * NN] * (O0[ii * 73 + c] + O1[ii * 73 + c]);
        }
        out[((size_t)b * (CC / 4) + g2) * NN + i0 + ii] = acc * inv;
    }
}

// ---------------------------------------------------------------------------
extern "C" void kernel_launch(void* const* d_in, const int* in_sizes, int n_in,
                              void* d_out, int out_size)
{
    const float* x  = (const float*)d_in[0];
    const float* Wq = (const float*)d_in[1];
    const float* bq = (const float*)d_in[2];
    const float* Wk = (const float*)d_in[3];
    const float* bk = (const float*)d_in[4];
    const float* Wv = (const float*)d_in[5];
    const float* bv = (const float*)d_in[6];
    float* out = (float*)d_out;

    const size_t shq = (size_t)(CC * TQ + 3 * CC * CC) * sizeof(float)
                     + 2u * 9216u * sizeof(__nv_bfloat16);
    cudaFuncSetAttribute(qkv_kernel,   cudaFuncAttributeMaxDynamicSharedMemorySize, (int)shq);
    cudaFuncSetAttribute(flash_kernel, cudaFuncAttributeMaxDynamicSharedMemorySize, SM_TOTAL);

    qkv_kernel<<<BB * NQT, 256, shq>>>(x, Wq, bq, Wk, bk, Wv, bv);
    flash_kernel<<<BB * NQT, 256, SM_TOTAL>>>(x, out);
}